// round 7
// baseline (speedup 1.0000x reference)
#include <cuda_runtime.h>
#include <cstddef>

#define NN 100000
#define NE 3200000
#define FIN 512
#define HID 64
#define NC  64
#define KHOPS 20

// ---------------- scratch (device globals; no allocation allowed) ------------
__device__ float g_h[(size_t)NN * HID];      // MLP hidden
__device__ short g_qA[(size_t)NN * NC];      // ping: int16 state (row-scaled)
__device__ short g_qB[(size_t)NN * NC];      // pong
__device__ float g_sA[NN];                   // per-row scales for qA
__device__ float g_sB[NN];
__device__ int   g_counts[NN];
__device__ int   g_rowptr[NN + 1];
__device__ int   g_widx[NN];
__device__ int2  g_edges[NE];                // (sender, weight-bits) grouped by receiver

// ---------------- CSR build --------------------------------------------------
__global__ void k_zero_counts() {
    int i = blockIdx.x * blockDim.x + threadIdx.x;
    if (i < NN) g_counts[i] = 0;
}

__global__ void k_hist(const int* __restrict__ rcv) {
    int e = blockIdx.x * blockDim.x + threadIdx.x;
    if (e < NE) atomicAdd(&g_counts[rcv[e]], 1);
}

__global__ void k_scan() {
    __shared__ int sm[1024];
    const int t = threadIdx.x;
    const int CH = (NN + 1023) / 1024;             // 98
    int beg = t * CH;
    int end = beg + CH; if (end > NN) end = NN;
    if (beg > NN) beg = NN;
    int s = 0;
    for (int i = beg; i < end; ++i) s += g_counts[i];
    sm[t] = s;
    __syncthreads();
    for (int d = 1; d < 1024; d <<= 1) {
        int add = (t >= d) ? sm[t - d] : 0;
        __syncthreads();
        sm[t] += add;
        __syncthreads();
    }
    int off = (t == 0) ? 0 : sm[t - 1];
    for (int i = beg; i < end; ++i) {
        g_rowptr[i] = off;
        g_widx[i]   = off;
        off += g_counts[i];
    }
    if (t == 1023) g_rowptr[NN] = sm[1023];
}

__global__ void k_scatter(const int* __restrict__ snd, const int* __restrict__ rcv,
                          const float* __restrict__ w) {
    int e = blockIdx.x * blockDim.x + threadIdx.x;
    if (e >= NE) return;
    int r = rcv[e];
    int pos = atomicAdd(&g_widx[r], 1);
    g_edges[pos] = make_int2(snd[e], __float_as_int(w[e]));
}

// ---------------- tiled fp32 GEMM1: h = relu(X[M,512]@W1+b1) -----------------
__global__ __launch_bounds__(256) void k_gemm1(const float* __restrict__ A,
                                               const float* __restrict__ B,
                                               const float* __restrict__ bias,
                                               float* __restrict__ C, int M) {
    constexpr int K = FIN, BM = 128, BN = 64, BK = 16;
    __shared__ float As[BK][BM + 4];
    __shared__ float Bs[BK][BN];
    const int tid = threadIdx.x;
    const int block_row = blockIdx.x * BM;
    const int tx = tid & 15;
    const int ty = tid >> 4;
    float acc[8][4];
#pragma unroll
    for (int i = 0; i < 8; ++i)
#pragma unroll
        for (int j = 0; j < 4; ++j) acc[i][j] = 0.f;

    const int ar = tid >> 2;
    const int ac = (tid & 3) << 2;
    const int br = tid >> 4;
    const int bc = (tid & 15) << 2;

    for (int k0 = 0; k0 < K; k0 += BK) {
#pragma unroll
        for (int i = 0; i < 2; ++i) {
            int row = block_row + ar + i * 64;
            float4 v = make_float4(0.f, 0.f, 0.f, 0.f);
            if (row < M) v = *(const float4*)(A + (size_t)row * K + k0 + ac);
            As[ac + 0][ar + i * 64] = v.x;
            As[ac + 1][ar + i * 64] = v.y;
            As[ac + 2][ar + i * 64] = v.z;
            As[ac + 3][ar + i * 64] = v.w;
        }
        *(float4*)&Bs[br][bc] = *(const float4*)(B + (size_t)(k0 + br) * BN + bc);
        __syncthreads();
#pragma unroll
        for (int kk = 0; kk < BK; ++kk) {
            float4 a0 = *(const float4*)&As[kk][ty * 8 + 0];
            float4 a1 = *(const float4*)&As[kk][ty * 8 + 4];
            float4 b0 = *(const float4*)&Bs[kk][tx * 4];
            float a[8] = {a0.x, a0.y, a0.z, a0.w, a1.x, a1.y, a1.z, a1.w};
            float b[4] = {b0.x, b0.y, b0.z, b0.w};
#pragma unroll
            for (int i = 0; i < 8; ++i)
#pragma unroll
                for (int j = 0; j < 4; ++j) acc[i][j] += a[i] * b[j];
        }
        __syncthreads();
    }
#pragma unroll
    for (int i = 0; i < 8; ++i) {
        int row = block_row + ty * 8 + i;
        if (row < M) {
            float4 v;
            v.x = fmaxf(acc[i][0] + bias[tx * 4 + 0], 0.f);
            v.y = fmaxf(acc[i][1] + bias[tx * 4 + 1], 0.f);
            v.z = fmaxf(acc[i][2] + bias[tx * 4 + 2], 0.f);
            v.w = fmaxf(acc[i][3] + bias[tx * 4 + 3], 0.f);
            *(float4*)(C + (size_t)row * BN + tx * 4) = v;
        }
    }
}

// ------ GEMM2 + fused hop-0 gating: quantized logits -> qA/sA, gate -> out ---
__global__ __launch_bounds__(256) void k_gemm2_gate(const float* __restrict__ A,
                                                    const float* __restrict__ B,
                                                    const float* __restrict__ bias,
                                                    const float* __restrict__ Wg,
                                                    const float* __restrict__ bg,
                                                    float* __restrict__ out, int M) {
    constexpr int BM = 128, BN = 64, BK = 16, K = HID;
    __shared__ float As[BK][BM + 4];
    __shared__ float Bs[BK][BN];
    const int tid = threadIdx.x;
    const int block_row = blockIdx.x * BM;
    const int tx = tid & 15;
    const int ty = tid >> 4;
    float acc[8][4];
#pragma unroll
    for (int i = 0; i < 8; ++i)
#pragma unroll
        for (int j = 0; j < 4; ++j) acc[i][j] = 0.f;

    const int ar = tid >> 2;
    const int ac = (tid & 3) << 2;
    const int br = tid >> 4;
    const int bc = (tid & 15) << 2;

    for (int k0 = 0; k0 < K; k0 += BK) {
#pragma unroll
        for (int i = 0; i < 2; ++i) {
            int row = block_row + ar + i * 64;
            float4 v = make_float4(0.f, 0.f, 0.f, 0.f);
            if (row < M) v = *(const float4*)(A + (size_t)row * K + k0 + ac);
            As[ac + 0][ar + i * 64] = v.x;
            As[ac + 1][ar + i * 64] = v.y;
            As[ac + 2][ar + i * 64] = v.z;
            As[ac + 3][ar + i * 64] = v.w;
        }
        *(float4*)&Bs[br][bc] = *(const float4*)(B + (size_t)(k0 + br) * BN + bc);
        __syncthreads();
#pragma unroll
        for (int kk = 0; kk < BK; ++kk) {
            float4 a0 = *(const float4*)&As[kk][ty * 8 + 0];
            float4 a1 = *(const float4*)&As[kk][ty * 8 + 4];
            float4 b0 = *(const float4*)&Bs[kk][tx * 4];
            float a[8] = {a0.x, a0.y, a0.z, a0.w, a1.x, a1.y, a1.z, a1.w};
            float b[4] = {b0.x, b0.y, b0.z, b0.w};
#pragma unroll
            for (int i = 0; i < 8; ++i)
#pragma unroll
                for (int j = 0; j < 4; ++j) acc[i][j] += a[i] * b[j];
        }
        __syncthreads();
    }
    float wgl[4];
#pragma unroll
    for (int j = 0; j < 4; ++j) wgl[j] = Wg[tx * 4 + j];
    float bgl = bg[0];
#pragma unroll
    for (int i = 0; i < 8; ++i) {
        float v0 = acc[i][0] + bias[tx * 4 + 0];
        float v1 = acc[i][1] + bias[tx * 4 + 1];
        float v2 = acc[i][2] + bias[tx * 4 + 2];
        float v3 = acc[i][3] + bias[tx * 4 + 3];
        // gate (16-lane group reduce)
        float part = v0 * wgl[0] + v1 * wgl[1] + v2 * wgl[2] + v3 * wgl[3];
#pragma unroll
        for (int o = 8; o; o >>= 1) part += __shfl_xor_sync(0xffffffffu, part, o);
        float gsc = 1.f / (1.f + __expf(-(part + bgl)));
        // row max (16-lane group reduce)
        float m = fmaxf(fmaxf(fabsf(v0), fabsf(v1)), fmaxf(fabsf(v2), fabsf(v3)));
#pragma unroll
        for (int o = 8; o; o >>= 1) m = fmaxf(m, __shfl_xor_sync(0xffffffffu, m, o));
        float inv = (m > 0.f) ? 32767.f / m : 0.f;
        int row = block_row + ty * 8 + i;
        if (row < M) {
            short2* q2 = (short2*)g_qA;
            q2[(size_t)row * 32 + tx * 2 + 0] =
                make_short2((short)__float2int_rn(v0 * inv), (short)__float2int_rn(v1 * inv));
            q2[(size_t)row * 32 + tx * 2 + 1] =
                make_short2((short)__float2int_rn(v2 * inv), (short)__float2int_rn(v3 * inv));
            if (tx == 0) g_sA[row] = m * (1.f / 32767.f);
            float4 o4 = make_float4(gsc * v0, gsc * v1, gsc * v2, gsc * v3);
            *(float4*)(out + (size_t)row * BN + tx * 4) = o4;
        }
    }
}

// ------ SpMM (gather CSR, int16 row-scaled state) + fused gated accumulation -
__global__ __launch_bounds__(256) void k_spmm_gate(int ab, int store_y,
                                                   const float* __restrict__ Wg,
                                                   const float* __restrict__ bg,
                                                   float* __restrict__ out) {
    int gw = (blockIdx.x * blockDim.x + threadIdx.x) >> 5;  // node (warp per node)
    int lane = threadIdx.x & 31;
    if (gw >= NN) return;
    const short2* __restrict__ x2 = ab ? (const short2*)g_qB : (const short2*)g_qA;
    const float*  __restrict__ xs = ab ? g_sB : g_sA;
    short2* __restrict__ y2       = ab ? (short2*)g_qA       : (short2*)g_qB;
    float*  __restrict__ ys       = ab ? g_sA : g_sB;

    int beg = g_rowptr[gw];
    int end = g_rowptr[gw + 1];
    float accx = 0.f, accy = 0.f;

    int e = beg;
    for (; e + 4 <= end; e += 4) {
        int2 e0 = g_edges[e + 0];
        int2 e1 = g_edges[e + 1];
        int2 e2 = g_edges[e + 2];
        int2 e3 = g_edges[e + 3];
        float ws0 = __int_as_float(e0.y) * xs[e0.x];
        float ws1 = __int_as_float(e1.y) * xs[e1.x];
        float ws2 = __int_as_float(e2.y) * xs[e2.x];
        float ws3 = __int_as_float(e3.y) * xs[e3.x];
        short2 q0 = x2[(size_t)e0.x * 32 + lane];
        short2 q1 = x2[(size_t)e1.x * 32 + lane];
        short2 q2 = x2[(size_t)e2.x * 32 + lane];
        short2 q3 = x2[(size_t)e3.x * 32 + lane];
        accx += ws0 * (float)q0.x; accy += ws0 * (float)q0.y;
        accx += ws1 * (float)q1.x; accy += ws1 * (float)q1.y;
        accx += ws2 * (float)q2.x; accy += ws2 * (float)q2.y;
        accx += ws3 * (float)q3.x; accy += ws3 * (float)q3.y;
    }
    for (; e < end; ++e) {
        int2 ep = g_edges[e];
        float ws = __int_as_float(ep.y) * xs[ep.x];
        short2 q = x2[(size_t)ep.x * 32 + lane];
        accx += ws * (float)q.x; accy += ws * (float)q.y;
    }
    // accx/accy are TRUE y values (scales folded in)

    if (store_y) {
        float m = fmaxf(fabsf(accx), fabsf(accy));
#pragma unroll
        for (int o = 16; o; o >>= 1) m = fmaxf(m, __shfl_xor_sync(0xffffffffu, m, o));
        float inv = (m > 0.f) ? 32767.f / m : 0.f;
        y2[(size_t)gw * 32 + lane] =
            make_short2((short)__float2int_rn(accx * inv), (short)__float2int_rn(accy * inv));
        if (lane == 0) ys[gw] = m * (1.f / 32767.f);
    }

    // fused gated-sum accumulation
    float part = accx * Wg[2 * lane] + accy * Wg[2 * lane + 1];
#pragma unroll
    for (int o = 16; o; o >>= 1) part += __shfl_xor_sync(0xffffffffu, part, o);
    float gsc = 1.f / (1.f + __expf(-(part + bg[0])));
    float2* o2 = (float2*)out;
    float2 cur = o2[(size_t)gw * 32 + lane];
    cur.x += gsc * accx;
    cur.y += gsc * accy;
    o2[(size_t)gw * 32 + lane] = cur;
}

// ---------------- launch -----------------------------------------------------
extern "C" void kernel_launch(void* const* d_in, const int* in_sizes, int n_in,
                              void* d_out, int out_size) {
    const float* X   = (const float*)d_in[0];
    const float* ew  = (const float*)d_in[1];
    const float* W1  = (const float*)d_in[2];
    const float* b1  = (const float*)d_in[3];
    const float* W2  = (const float*)d_in[4];
    const float* b2  = (const float*)d_in[5];
    const float* Wg  = (const float*)d_in[6];
    const float* bg  = (const float*)d_in[7];
    const int*   snd = (const int*)d_in[8];
    const int*   rcv = (const int*)d_in[9];
    float* out = (float*)d_out;

    void* p;
    cudaGetSymbolAddress(&p, g_h);  float* hptr = (float*)p;

    // CSR build (once per launch)
    k_zero_counts<<<(NN + 255) / 256, 256>>>();
    k_hist<<<(NE + 255) / 256, 256>>>(rcv);
    k_scan<<<1, 1024>>>();
    k_scatter<<<(NE + 255) / 256, 256>>>(snd, rcv, ew);

    // MLP: h = relu(X@W1+b1); logits -> quantized qA/sA + fused hop-0 gate -> out
    k_gemm1<<<(NN + 127) / 128, 256>>>(X, W1, b1, hptr, NN);
    k_gemm2_gate<<<(NN + 127) / 128, 256>>>(hptr, W2, b2, Wg, bg, out, NN);

    // 20 propagations, ping-pong int16 row-scaled state
    const int SPB = (NN + 7) / 8;   // 8 warps/block
    for (int k = 0; k < KHOPS; ++k)
        k_spmm_gate<<<SPB, 256>>>(k & 1, (k < KHOPS - 1) ? 1 : 0, Wg, bg, out);
}

// round 8
// speedup vs baseline: 1.0522x; 1.0522x over previous
#include <cuda_runtime.h>
#include <cstddef>

#define NN 100000
#define NE 3200000
#define FIN 512
#define HID 64
#define NC  64
#define KHOPS 20

// ---------------- scratch (device globals; no allocation allowed) ------------
__device__ float g_h[(size_t)NN * HID];      // MLP hidden
__device__ short g_qA[(size_t)NN * NC];      // ping: int16 state (row-scaled)
__device__ short g_qB[(size_t)NN * NC];      // pong
__device__ float g_sA[NN];                   // per-row scales for qA
__device__ float g_sB[NN];
__device__ int   g_counts[NN];
__device__ int   g_rowptr[NN + 1];
__device__ int   g_widx[NN];
__device__ int2  g_edges[NE];                // (sender, weight-bits) grouped by receiver

// ---------------- CSR build --------------------------------------------------
__global__ void k_zero_counts() {
    int i = blockIdx.x * blockDim.x + threadIdx.x;
    if (i < NN) g_counts[i] = 0;
}

__global__ void k_hist(const int* __restrict__ rcv) {
    int e = blockIdx.x * blockDim.x + threadIdx.x;
    if (e < NE) atomicAdd(&g_counts[rcv[e]], 1);
}

__global__ void k_scan() {
    __shared__ int sm[1024];
    const int t = threadIdx.x;
    const int CH = (NN + 1023) / 1024;             // 98
    int beg = t * CH;
    int end = beg + CH; if (end > NN) end = NN;
    if (beg > NN) beg = NN;
    int s = 0;
    for (int i = beg; i < end; ++i) s += g_counts[i];
    sm[t] = s;
    __syncthreads();
    for (int d = 1; d < 1024; d <<= 1) {
        int add = (t >= d) ? sm[t - d] : 0;
        __syncthreads();
        sm[t] += add;
        __syncthreads();
    }
    int off = (t == 0) ? 0 : sm[t - 1];
    for (int i = beg; i < end; ++i) {
        g_rowptr[i] = off;
        g_widx[i]   = off;
        off += g_counts[i];
    }
    if (t == 1023) g_rowptr[NN] = sm[1023];
}

__global__ void k_scatter(const int* __restrict__ snd, const int* __restrict__ rcv,
                          const float* __restrict__ w) {
    int e = blockIdx.x * blockDim.x + threadIdx.x;
    if (e >= NE) return;
    int r = rcv[e];
    int pos = atomicAdd(&g_widx[r], 1);
    g_edges[pos] = make_int2(snd[e], __float_as_int(w[e]));
}

// ---------------- tiled fp32 GEMM1: h = relu(X[M,512]@W1+b1) -----------------
__global__ __launch_bounds__(256) void k_gemm1(const float* __restrict__ A,
                                               const float* __restrict__ B,
                                               const float* __restrict__ bias,
                                               float* __restrict__ C, int M) {
    constexpr int K = FIN, BM = 128, BN = 64, BK = 16;
    __shared__ float As[BK][BM + 4];
    __shared__ float Bs[BK][BN];
    const int tid = threadIdx.x;
    const int block_row = blockIdx.x * BM;
    const int tx = tid & 15;
    const int ty = tid >> 4;
    float acc[8][4];
#pragma unroll
    for (int i = 0; i < 8; ++i)
#pragma unroll
        for (int j = 0; j < 4; ++j) acc[i][j] = 0.f;

    const int ar = tid >> 2;
    const int ac = (tid & 3) << 2;
    const int br = tid >> 4;
    const int bc = (tid & 15) << 2;

    for (int k0 = 0; k0 < K; k0 += BK) {
#pragma unroll
        for (int i = 0; i < 2; ++i) {
            int row = block_row + ar + i * 64;
            float4 v = make_float4(0.f, 0.f, 0.f, 0.f);
            if (row < M) v = *(const float4*)(A + (size_t)row * K + k0 + ac);
            As[ac + 0][ar + i * 64] = v.x;
            As[ac + 1][ar + i * 64] = v.y;
            As[ac + 2][ar + i * 64] = v.z;
            As[ac + 3][ar + i * 64] = v.w;
        }
        *(float4*)&Bs[br][bc] = *(const float4*)(B + (size_t)(k0 + br) * BN + bc);
        __syncthreads();
#pragma unroll
        for (int kk = 0; kk < BK; ++kk) {
            float4 a0 = *(const float4*)&As[kk][ty * 8 + 0];
            float4 a1 = *(const float4*)&As[kk][ty * 8 + 4];
            float4 b0 = *(const float4*)&Bs[kk][tx * 4];
            float a[8] = {a0.x, a0.y, a0.z, a0.w, a1.x, a1.y, a1.z, a1.w};
            float b[4] = {b0.x, b0.y, b0.z, b0.w};
#pragma unroll
            for (int i = 0; i < 8; ++i)
#pragma unroll
                for (int j = 0; j < 4; ++j) acc[i][j] += a[i] * b[j];
        }
        __syncthreads();
    }
#pragma unroll
    for (int i = 0; i < 8; ++i) {
        int row = block_row + ty * 8 + i;
        if (row < M) {
            float4 v;
            v.x = fmaxf(acc[i][0] + bias[tx * 4 + 0], 0.f);
            v.y = fmaxf(acc[i][1] + bias[tx * 4 + 1], 0.f);
            v.z = fmaxf(acc[i][2] + bias[tx * 4 + 2], 0.f);
            v.w = fmaxf(acc[i][3] + bias[tx * 4 + 3], 0.f);
            *(float4*)(C + (size_t)row * BN + tx * 4) = v;
        }
    }
}

// ------ GEMM2 + fused hop-0 gating: quantized logits -> qA/sA, gate -> out ---
__global__ __launch_bounds__(256) void k_gemm2_gate(const float* __restrict__ A,
                                                    const float* __restrict__ B,
                                                    const float* __restrict__ bias,
                                                    const float* __restrict__ Wg,
                                                    const float* __restrict__ bg,
                                                    float* __restrict__ out, int M) {
    constexpr int BM = 128, BN = 64, BK = 16, K = HID;
    __shared__ float As[BK][BM + 4];
    __shared__ float Bs[BK][BN];
    const int tid = threadIdx.x;
    const int block_row = blockIdx.x * BM;
    const int tx = tid & 15;
    const int ty = tid >> 4;
    float acc[8][4];
#pragma unroll
    for (int i = 0; i < 8; ++i)
#pragma unroll
        for (int j = 0; j < 4; ++j) acc[i][j] = 0.f;

    const int ar = tid >> 2;
    const int ac = (tid & 3) << 2;
    const int br = tid >> 4;
    const int bc = (tid & 15) << 2;

    for (int k0 = 0; k0 < K; k0 += BK) {
#pragma unroll
        for (int i = 0; i < 2; ++i) {
            int row = block_row + ar + i * 64;
            float4 v = make_float4(0.f, 0.f, 0.f, 0.f);
            if (row < M) v = *(const float4*)(A + (size_t)row * K + k0 + ac);
            As[ac + 0][ar + i * 64] = v.x;
            As[ac + 1][ar + i * 64] = v.y;
            As[ac + 2][ar + i * 64] = v.z;
            As[ac + 3][ar + i * 64] = v.w;
        }
        *(float4*)&Bs[br][bc] = *(const float4*)(B + (size_t)(k0 + br) * BN + bc);
        __syncthreads();
#pragma unroll
        for (int kk = 0; kk < BK; ++kk) {
            float4 a0 = *(const float4*)&As[kk][ty * 8 + 0];
            float4 a1 = *(const float4*)&As[kk][ty * 8 + 4];
            float4 b0 = *(const float4*)&Bs[kk][tx * 4];
            float a[8] = {a0.x, a0.y, a0.z, a0.w, a1.x, a1.y, a1.z, a1.w};
            float b[4] = {b0.x, b0.y, b0.z, b0.w};
#pragma unroll
            for (int i = 0; i < 8; ++i)
#pragma unroll
                for (int j = 0; j < 4; ++j) acc[i][j] += a[i] * b[j];
        }
        __syncthreads();
    }
    float wgl[4];
#pragma unroll
    for (int j = 0; j < 4; ++j) wgl[j] = Wg[tx * 4 + j];
    float bgl = bg[0];
#pragma unroll
    for (int i = 0; i < 8; ++i) {
        float v0 = acc[i][0] + bias[tx * 4 + 0];
        float v1 = acc[i][1] + bias[tx * 4 + 1];
        float v2 = acc[i][2] + bias[tx * 4 + 2];
        float v3 = acc[i][3] + bias[tx * 4 + 3];
        // gate (16-lane group reduce)
        float part = v0 * wgl[0] + v1 * wgl[1] + v2 * wgl[2] + v3 * wgl[3];
#pragma unroll
        for (int o = 8; o; o >>= 1) part += __shfl_xor_sync(0xffffffffu, part, o);
        float gsc = 1.f / (1.f + __expf(-(part + bgl)));
        // row max (16-lane group reduce)
        float m = fmaxf(fmaxf(fabsf(v0), fabsf(v1)), fmaxf(fabsf(v2), fabsf(v3)));
#pragma unroll
        for (int o = 8; o; o >>= 1) m = fmaxf(m, __shfl_xor_sync(0xffffffffu, m, o));
        float inv = (m > 0.f) ? 32767.f / m : 0.f;
        int row = block_row + ty * 8 + i;
        if (row < M) {
            short2* q2 = (short2*)g_qA;
            q2[(size_t)row * 32 + tx * 2 + 0] =
                make_short2((short)__float2int_rn(v0 * inv), (short)__float2int_rn(v1 * inv));
            q2[(size_t)row * 32 + tx * 2 + 1] =
                make_short2((short)__float2int_rn(v2 * inv), (short)__float2int_rn(v3 * inv));
            if (tx == 0) g_sA[row] = m * (1.f / 32767.f);
            float4 o4 = make_float4(gsc * v0, gsc * v1, gsc * v2, gsc * v3);
            *(float4*)(out + (size_t)row * BN + tx * 4) = o4;
        }
    }
}

// ------ SpMM: int16 state, 32-wide batched scale loads + shfl broadcast ------
__global__ __launch_bounds__(256) void k_spmm_gate(int ab, int store_y,
                                                   const float* __restrict__ Wg,
                                                   const float* __restrict__ bg,
                                                   float* __restrict__ out) {
    int gw = (blockIdx.x * blockDim.x + threadIdx.x) >> 5;  // node (warp per node)
    int lane = threadIdx.x & 31;
    if (gw >= NN) return;
    const short2* __restrict__ x2 = ab ? (const short2*)g_qB : (const short2*)g_qA;
    const float*  __restrict__ xs = ab ? g_sB : g_sA;
    short2* __restrict__ y2       = ab ? (short2*)g_qA       : (short2*)g_qB;
    float*  __restrict__ ys       = ab ? g_sA : g_sB;

    const int beg = g_rowptr[gw];
    const int end = g_rowptr[gw + 1];
    float accx = 0.f, accy = 0.f;

    int base = beg;
    // full 32-edge chunks: lane-parallel edge+scale preload, unrolled gather
    for (; base + 32 <= end; base += 32) {
        int2 ep = g_edges[base + lane];
        int   snd = ep.x;
        float ws  = __int_as_float(ep.y) * xs[snd];
#pragma unroll
        for (int j = 0; j < 32; ++j) {
            int   s_j = __shfl_sync(0xffffffffu, snd, j);
            float w_j = __shfl_sync(0xffffffffu, ws,  j);
            short2 q = x2[(size_t)s_j * 32 + lane];
            accx += w_j * (float)q.x;
            accy += w_j * (float)q.y;
        }
    }
    // remainder chunk
    if (base < end) {
        int idx = base + lane;
        int snd = 0; float ws = 0.f;
        if (idx < end) {
            int2 ep = g_edges[idx];
            snd = ep.x;
            ws  = __int_as_float(ep.y) * xs[snd];
        }
        int cnt = end - base;
        for (int j = 0; j < cnt; ++j) {
            int   s_j = __shfl_sync(0xffffffffu, snd, j);
            float w_j = __shfl_sync(0xffffffffu, ws,  j);
            short2 q = x2[(size_t)s_j * 32 + lane];
            accx += w_j * (float)q.x;
            accy += w_j * (float)q.y;
        }
    }
    // accx/accy are TRUE y values (scales folded in)

    if (store_y) {
        float m = fmaxf(fabsf(accx), fabsf(accy));
#pragma unroll
        for (int o = 16; o; o >>= 1) m = fmaxf(m, __shfl_xor_sync(0xffffffffu, m, o));
        float inv = (m > 0.f) ? 32767.f / m : 0.f;
        y2[(size_t)gw * 32 + lane] =
            make_short2((short)__float2int_rn(accx * inv), (short)__float2int_rn(accy * inv));
        if (lane == 0) ys[gw] = m * (1.f / 32767.f);
    }

    // fused gated-sum accumulation
    float part = accx * Wg[2 * lane] + accy * Wg[2 * lane + 1];
#pragma unroll
    for (int o = 16; o; o >>= 1) part += __shfl_xor_sync(0xffffffffu, part, o);
    float gsc = 1.f / (1.f + __expf(-(part + bg[0])));
    float2* o2 = (float2*)out;
    float2 cur = o2[(size_t)gw * 32 + lane];
    cur.x += gsc * accx;
    cur.y += gsc * accy;
    o2[(size_t)gw * 32 + lane] = cur;
}

// ---------------- launch -----------------------------------------------------
extern "C" void kernel_launch(void* const* d_in, const int* in_sizes, int n_in,
                              void* d_out, int out_size) {
    const float* X   = (const float*)d_in[0];
    const float* ew  = (const float*)d_in[1];
    const float* W1  = (const float*)d_in[2];
    const float* b1  = (const float*)d_in[3];
    const float* W2  = (const float*)d_in[4];
    const float* b2  = (const float*)d_in[5];
    const float* Wg  = (const float*)d_in[6];
    const float* bg  = (const float*)d_in[7];
    const int*   snd = (const int*)d_in[8];
    const int*   rcv = (const int*)d_in[9];
    float* out = (float*)d_out;

    void* p;
    cudaGetSymbolAddress(&p, g_h);  float* hptr = (float*)p;

    // CSR build (once per launch)
    k_zero_counts<<<(NN + 255) / 256, 256>>>();
    k_hist<<<(NE + 255) / 256, 256>>>(rcv);
    k_scan<<<1, 1024>>>();
    k_scatter<<<(NE + 255) / 256, 256>>>(snd, rcv, ew);

    // MLP: h = relu(X@W1+b1); logits -> quantized qA/sA + fused hop-0 gate -> out
    k_gemm1<<<(NN + 127) / 128, 256>>>(X, W1, b1, hptr, NN);
    k_gemm2_gate<<<(NN + 127) / 128, 256>>>(hptr, W2, b2, Wg, bg, out, NN);

    // 20 propagations, ping-pong int16 row-scaled state
    const int SPB = (NN + 7) / 8;   // 8 warps/block
    for (int k = 0; k < KHOPS; ++k)
        k_spmm_gate<<<SPB, 256>>>(k & 1, (k < KHOPS - 1) ? 1 : 0, Wg, bg, out);
}